// round 9
// baseline (speedup 1.0000x reference)
#include <cuda_runtime.h>
#include <cuda_fp16.h>
#include <math.h>

#define BB 2
#define LL 2048
#define SS 2048
#define HH 16
#define EE 64
#define TQ 64
#define TK 64
#define PITCH 144  // smem row pitch: 64 fp16 (128B) + 16B pad

#define NELEM (BB * HH * LL * EE)

__device__ __align__(16) __half gQ[NELEM];
__device__ __align__(16) __half gK[NELEM];
__device__ __align__(16) __half gV[NELEM];

// ---------------- helpers ----------------
__device__ __forceinline__ unsigned smem_u32(const void* p) {
    unsigned a;
    asm("{ .reg .u64 t; cvta.to.shared.u64 t, %1; cvt.u32.u64 %0, t; }"
        : "=r"(a) : "l"(p));
    return a;
}
#define CP16(dst, src) \
    asm volatile("cp.async.cg.shared.global [%0], [%1], 16;" :: "r"(dst), "l"(src))
#define CP_COMMIT() asm volatile("cp.async.commit_group;" ::: "memory")
#define CP_WAIT0()  asm volatile("cp.async.wait_group 0;" ::: "memory")
#define CP_WAIT2()  asm volatile("cp.async.wait_group 2;" ::: "memory")

__device__ __forceinline__ void ldsm4(unsigned r[4], unsigned addr) {
    asm volatile("ldmatrix.sync.aligned.m8n8.x4.shared.b16 {%0,%1,%2,%3}, [%4];"
                 : "=r"(r[0]), "=r"(r[1]), "=r"(r[2]), "=r"(r[3]) : "r"(addr));
}
__device__ __forceinline__ void ldsm4t(unsigned r[4], unsigned addr) {
    asm volatile("ldmatrix.sync.aligned.m8n8.x4.trans.shared.b16 {%0,%1,%2,%3}, [%4];"
                 : "=r"(r[0]), "=r"(r[1]), "=r"(r[2]), "=r"(r[3]) : "r"(addr));
}
__device__ __forceinline__ void mma16816(float* c, const unsigned a[4],
                                         unsigned b0, unsigned b1) {
    asm volatile(
        "mma.sync.aligned.m16n8k16.row.col.f32.f16.f16.f32 "
        "{%0,%1,%2,%3}, {%4,%5,%6,%7}, {%8,%9}, {%0,%1,%2,%3};"
        : "+f"(c[0]), "+f"(c[1]), "+f"(c[2]), "+f"(c[3])
        : "r"(a[0]), "r"(a[1]), "r"(a[2]), "r"(a[3]), "r"(b0), "r"(b1));
}
__device__ __forceinline__ unsigned pack2h(float lo, float hi) {
    __half2 p = __floats2half2_rn(lo, hi);
    return *reinterpret_cast<unsigned*>(&p);
}
__device__ __forceinline__ float ex2(float x) {
    float r;
    asm("ex2.approx.ftz.f32 %0, %1;" : "=f"(r) : "f"(x));
    return r;
}

// ---------------------------------------------------------------------------
// Prep: fp32 [b,s,h,e] -> fp16 [b,h,s,e]; Q scaled by 0.125*log2(e).
// ---------------------------------------------------------------------------
__global__ __launch_bounds__(256)
void prep(const float* __restrict__ Q, const float* __restrict__ K,
          const float* __restrict__ V) {
    const unsigned per = NELEM / 4;
    unsigned idx = blockIdx.x * 256u + threadIdx.x;
    if (idx >= 3u * per) return;
    const int t = idx / per;
    const unsigned c = idx % per;

    const unsigned e4 = c & 15;
    const unsigned r  = c >> 4;
    const unsigned h  = r & (HH - 1);
    const unsigned bs = r >> 4;
    const unsigned s  = bs & (LL - 1);
    const unsigned b  = bs >> 11;

    const float* src = (t == 0) ? Q : (t == 1) ? K : V;
    float4 v = *(const float4*)(src + (size_t)c * 4);
    if (t == 0) {
        const float sc = 0.18033688011112042f;  // 0.125 * log2(e)
        v.x *= sc; v.y *= sc; v.z *= sc; v.w *= sc;
    }
    __half* oh = (t == 0) ? gQ : (t == 1) ? gK : gV;
    const size_t o = (((size_t)(b * HH + h) * LL + s) * EE) + e4 * 4;
    *(uint2*)(oh + o) = make_uint2(pack2h(v.x, v.y), pack2h(v.z, v.w));
}

// ---------------------------------------------------------------------------
// Fused attention. TQ=64, 8 warps: warp = (row group wr 0..3) x (col half wc).
// Sweep 1: row sums with a 4-deep K pipeline. Sweep 2: recompute S, write
// normalized A and O directly; O reduced across the two col-half warps.
// ---------------------------------------------------------------------------
__global__ __launch_bounds__(256, 3)
void attn_tc(float* __restrict__ Aout, float* __restrict__ Vout) {
    extern __shared__ char sm[];
    const unsigned uS = smem_u32(sm);
    const unsigned uQ = uS;                        // 9216
    // 4 KV buffer slots of 9216 each
#define BUF(i) (uS + 9216u + (unsigned)(i) * 9216u)
    const unsigned uR = uS + 46080u;               // rowsum halves: 2 x 64 floats

    const int tid  = threadIdx.x;
    const int lane = tid & 31;
    const int w    = tid >> 5;       // 0..7
    const int wr   = w >> 1;         // row group 0..3
    const int wc   = w & 1;          // col half 0/1
    const int g    = lane >> 2;
    const int tig  = lane & 3;

    const int bh = blockIdx.y;
    const int b  = bh / HH, h = bh % HH;
    const int qt = (int)gridDim.x - 1 - (int)blockIdx.x;  // heavy tiles first
    const int q0 = qt * TQ;

    const size_t qbase  = ((size_t)bh * LL + q0) * EE;
    const size_t kvbase = (size_t)bh * LL * EE;
    const int nkt = qt + 1;

    // ---- issue Q tile; pre-issue K0..K2 as 3 groups (commit unconditionally) ----
    for (int c = tid; c < 512; c += 256) {
        const int i = c >> 3, ch = c & 7;
        CP16(uQ + i * PITCH + ch * 16, gQ + qbase + (size_t)i * EE + ch * 8);
    }
    for (int p = 0; p < 3; ++p) {
        if (p < nkt) {
            const size_t rb = kvbase + (size_t)p * TK * EE;
            for (int c = tid; c < 512; c += 256) {
                const int i = c >> 3, ch = c & 7;
                CP16(BUF(p) + i * PITCH + ch * 16, gK + rb + (size_t)i * EE + ch * 8);
            }
        }
        CP_COMMIT();
    }

    const int lr  = (lane & 7) + ((lane >> 3) & 1) * 8;
    const int lco = (lane >> 4) * 8;
    const unsigned qrow = (unsigned)((wr * 16 + lr) * PITCH + lco * 2);
    const unsigned krow = (unsigned)(lr * PITCH + lco * 2);

    const int gi0 = q0 + wr * 16 + g;
    const int gi1 = gi0 + 8;
    const int colbase = wc * 32;

    float rsum0 = 0.0f, rsum1 = 0.0f;

    // ================= sweep 1: row sums (K ring of 4, distance 3) ==========
    for (int kt = 0; kt < nkt; ++kt) {
        CP_WAIT2();           // groups newer than kt's: exactly 2 -> K(kt) ready
        __syncthreads();
        if (kt + 3 < nkt) {   // issue K(kt+3) into the slot freed at kt-1
            const size_t rb = kvbase + (size_t)(kt + 3) * TK * EE;
            const unsigned uN = BUF((kt + 3) & 3);
            for (int c = tid; c < 512; c += 256) {
                const int i = c >> 3, ch = c & 7;
                CP16(uN + i * PITCH + ch * 16, gK + rb + (size_t)i * EE + ch * 8);
            }
        }
        CP_COMMIT();
        const unsigned uK = BUF(kt & 3);

        float s[4][4];
#pragma unroll
        for (int nb = 0; nb < 4; ++nb)
#pragma unroll
            for (int c = 0; c < 4; ++c) s[nb][c] = 0.0f;
#pragma unroll
        for (int ks = 0; ks < 4; ++ks) {
            unsigned qf[4];
            ldsm4(qf, uQ + qrow + ks * 32);
#pragma unroll
            for (int jg = 0; jg < 2; ++jg) {
                unsigned kf[4];
                ldsm4(kf, uK + (colbase + jg * 16) * PITCH + krow + ks * 32);
                mma16816(s[2 * jg],     qf, kf[0], kf[2]);
                mma16816(s[2 * jg + 1], qf, kf[1], kf[3]);
            }
        }
        const int k0 = kt * TK;
        const bool anymask = (k0 + colbase + 32 > gi0);
#pragma unroll
        for (int nb = 0; nb < 4; ++nb) {
            const int cj = k0 + colbase + nb * 8 + 2 * tig;
            float e0 = ex2(s[nb][0]);
            float e1 = ex2(s[nb][1]);
            float e2 = ex2(s[nb][2]);
            float e3 = ex2(s[nb][3]);
            if (anymask) {
                if (cj     > gi0) e0 = 0.0f;
                if (cj + 1 > gi0) e1 = 0.0f;
                if (cj     > gi1) e2 = 0.0f;
                if (cj + 1 > gi1) e3 = 0.0f;
            }
            rsum0 += e0 + e1;
            rsum1 += e2 + e3;
        }
    }

    // tig-reduce, publish col-half partials, combine
    rsum0 += __shfl_xor_sync(0xffffffffu, rsum0, 1);
    rsum0 += __shfl_xor_sync(0xffffffffu, rsum0, 2);
    rsum1 += __shfl_xor_sync(0xffffffffu, rsum1, 1);
    rsum1 += __shfl_xor_sync(0xffffffffu, rsum1, 2);
    if (tig == 0) {
        *(float*)(sm + (uR - uS) + (wc * 64 + wr * 16 + g) * 4)     = rsum0;
        *(float*)(sm + (uR - uS) + (wc * 64 + wr * 16 + g + 8) * 4) = rsum1;
    }
    CP_WAIT0();
    __syncthreads();
    const float inv0 = 1.0f / (*(float*)(sm + (uR - uS) + (wr * 16 + g) * 4) +
                               *(float*)(sm + (uR - uS) + (64 + wr * 16 + g) * 4));
    const float inv1 = 1.0f / (*(float*)(sm + (uR - uS) + (wr * 16 + g + 8) * 4) +
                               *(float*)(sm + (uR - uS) + (64 + wr * 16 + g + 8) * 4));

    // ---- issue K0+V0 for sweep 2 (K in BUF0/1, V in BUF2/3), then zero-fill ----
    for (int c = tid; c < 1024; c += 256) {
        const int arr = c >> 9, i = (c >> 3) & 63, ch = c & 7;
        const __half* gsrc = arr ? gV : gK;
        const unsigned dst = arr ? BUF(2) : BUF(0);
        CP16(dst + i * PITCH + ch * 16, gsrc + kvbase + (size_t)i * EE + ch * 8);
    }
    CP_COMMIT();

    if (Aout) {
        const int c0 = q0 + TQ;
        const int w4 = (SS - c0) >> 2;
        if (w4 > 0) {
            const float4 z = make_float4(0.f, 0.f, 0.f, 0.f);
            float* Abase = Aout + ((size_t)bh * LL + q0) * SS + c0;
            for (int i = tid; i < TQ * w4; i += 256) {
                const int r = i / w4;
                const int c = i - r * w4;
                __stcs((float4*)(Abase + (size_t)r * SS + 4 * c), z);
            }
        }
    }

    float o[8][4];
#pragma unroll
    for (int nb = 0; nb < 8; ++nb)
#pragma unroll
        for (int c = 0; c < 4; ++c) o[nb][c] = 0.0f;

    // ================= sweep 2: normalized A + O =================
    for (int kt = 0; kt < nkt; ++kt) {
        const int k0 = kt * TK;
        CP_WAIT0();
        __syncthreads();
        if (kt + 1 < nkt) {
            const unsigned nb1 = (kt + 1) & 1;
            const size_t rb = kvbase + (size_t)(kt + 1) * TK * EE;
            for (int c = tid; c < 1024; c += 256) {
                const int arr = c >> 9, i = (c >> 3) & 63, ch = c & 7;
                const __half* gsrc = arr ? gV : gK;
                const unsigned base = arr ? BUF(2 + nb1) : BUF(nb1);
                CP16(base + i * PITCH + ch * 16, gsrc + rb + (size_t)i * EE + ch * 8);
            }
        }
        CP_COMMIT();
        const unsigned uK = BUF(kt & 1);
        const unsigned uV = BUF(2 + (kt & 1));

        float s[4][4];
#pragma unroll
        for (int nb = 0; nb < 4; ++nb)
#pragma unroll
            for (int c = 0; c < 4; ++c) s[nb][c] = 0.0f;
#pragma unroll
        for (int ks = 0; ks < 4; ++ks) {
            unsigned qf[4];
            ldsm4(qf, uQ + qrow + ks * 32);
#pragma unroll
            for (int jg = 0; jg < 2; ++jg) {
                unsigned kf[4];
                ldsm4(kf, uK + (colbase + jg * 16) * PITCH + krow + ks * 32);
                mma16816(s[2 * jg],     qf, kf[0], kf[2]);
                mma16816(s[2 * jg + 1], qf, kf[1], kf[3]);
            }
        }

        const bool anymask = (k0 + colbase + 32 > gi0);
        float* A0 = Aout ? (Aout + ((size_t)bh * LL + gi0) * SS + k0 + colbase) : (float*)0;
        float* A1 = Aout ? (Aout + ((size_t)bh * LL + gi1) * SS + k0 + colbase) : (float*)0;

#pragma unroll
        for (int ks2 = 0; ks2 < 2; ++ks2) {   // two 16-j chunks of this col half
            unsigned ah[4];
#pragma unroll
            for (int half = 0; half < 2; ++half) {
                const int nb = 2 * ks2 + half;
                const int cj = k0 + colbase + nb * 8 + 2 * tig;
                float e0 = ex2(s[nb][0]);
                float e1 = ex2(s[nb][1]);
                float e2 = ex2(s[nb][2]);
                float e3 = ex2(s[nb][3]);
                if (anymask) {
                    if (cj     > gi0) e0 = 0.0f;
                    if (cj + 1 > gi0) e1 = 0.0f;
                    if (cj     > gi1) e2 = 0.0f;
                    if (cj + 1 > gi1) e3 = 0.0f;
                }
                e0 *= inv0; e1 *= inv0; e2 *= inv1; e3 *= inv1;
                if (A0) {
                    __stcs((float2*)(A0 + nb * 8 + 2 * tig), make_float2(e0, e1));
                    __stcs((float2*)(A1 + nb * 8 + 2 * tig), make_float2(e2, e3));
                }
                ah[2 * half]     = pack2h(e0, e1);
                ah[2 * half + 1] = pack2h(e2, e3);
            }
            const unsigned vbase = uV + (colbase + ks2 * 16) * PITCH + krow;
#pragma unroll
            for (int dg = 0; dg < 4; ++dg) {
                unsigned vf[4];
                ldsm4t(vf, vbase + dg * 32);
                mma16816(o[2 * dg],     ah, vf[0], vf[1]);
                mma16816(o[2 * dg + 1], ah, vf[2], vf[3]);
            }
        }
    }

    // ---- O: reduce col-half partials across warp pairs, write out ----
    if (Vout) {
        __syncthreads();  // all smem K/V reads done; BUF area reusable
        // staging region per wr: 16 rows x 68-float pitch (bank-stagger)
        const unsigned ored = BUF(0) + (unsigned)wr * 4352u;
        if (wc == 0) {
#pragma unroll
            for (int nb = 0; nb < 8; ++nb) {
                *(float2*)(sm + (ored - uS) + (g * 68 + nb * 8 + 2 * tig) * 4) =
                    make_float2(o[nb][0], o[nb][1]);
                *(float2*)(sm + (ored - uS) + ((g + 8) * 68 + nb * 8 + 2 * tig) * 4) =
                    make_float2(o[nb][2], o[nb][3]);
            }
        }
        __syncthreads();
        if (wc == 1) {
            float* O0 = Vout + (((size_t)(b * LL + gi0) * HH + h) * EE);
            float* O1 = Vout + (((size_t)(b * LL + gi1) * HH + h) * EE);
#pragma unroll
            for (int nb = 0; nb < 8; ++nb) {
                float2 p0 = *(float2*)(sm + (ored - uS) + (g * 68 + nb * 8 + 2 * tig) * 4);
                float2 p1 = *(float2*)(sm + (ored - uS) + ((g + 8) * 68 + nb * 8 + 2 * tig) * 4);
                *(float2*)(O0 + nb * 8 + 2 * tig) =
                    make_float2(o[nb][0] + p0.x, o[nb][1] + p0.y);
                *(float2*)(O1 + nb * 8 + 2 * tig) =
                    make_float2(o[nb][2] + p1.x, o[nb][3] + p1.y);
            }
        }
    }
#undef BUF
}

// ---------------------------------------------------------------------------
extern "C" void kernel_launch(void* const* d_in, const int* in_sizes, int n_in,
                              void* d_out, int out_size) {
    const float* Q = (const float*)d_in[0];
    const float* K = (const float*)d_in[1];
    const float* V = (const float*)d_in[2];

    const int V_SIZE = BB * LL * HH * EE;
    const int A_SIZE = (int)((size_t)BB * HH * LL * SS);

    float* out  = (float*)d_out;
    float* Vout = 0;
    float* Aout = 0;
    if (out_size >= V_SIZE + A_SIZE) { Vout = out; Aout = out + V_SIZE; }
    else if (out_size == A_SIZE)     { Aout = out; }
    else                             { Vout = out; }

    const unsigned prep_total = 3u * (NELEM / 4);
    prep<<<(prep_total + 255u) / 256u, 256>>>(Q, K, V);

    const int smem = 46080 + 512;
    cudaFuncSetAttribute(attn_tc, cudaFuncAttributeMaxDynamicSharedMemorySize, smem);
    dim3 grid1(LL / TQ, BB * HH);
    attn_tc<<<grid1, 256, smem>>>(Aout, Vout);
}